// round 1
// baseline (speedup 1.0000x reference)
#include <cuda_runtime.h>
#include <cuda_bf16.h>
#include <math.h>
#include <stdint.h>

// ---------------------------------------------------------------------------
// Problem constants (fixed by setup_inputs)
// ---------------------------------------------------------------------------
#define BATCH 8
#define HGT   128
#define WID   128
#define CH    192
#define NHEAD 6
#define HD    32
#define WS    8
#define SS    4
#define NTOK  64                      // tokens per window (WS*WS)
#define NWIN  (BATCH * 16 * 16)       // 2048 windows
#define TOT   (BATCH * HGT * WID)     // 131072 tokens
#define HID   (CH * 4)                // 768

// ---------------------------------------------------------------------------
// Scratch (static device globals; allocation-free)
// ---------------------------------------------------------------------------
__device__ float g_xw  [(size_t)NWIN * NTOK * CH];        // LN1 + shift + partition
__device__ float g_qkv [(size_t)NWIN * NTOK * 3 * CH];    // qkv
__device__ float g_attn[(size_t)NWIN * NTOK * CH];        // attention out (window layout)
__device__ float g_proj[(size_t)NWIN * NTOK * CH];        // proj out (window layout)
__device__ float g_x1  [(size_t)TOT * CH];                // residual 1
__device__ float g_ln2 [(size_t)TOT * CH];                // LN2 output
__device__ float g_h1  [(size_t)TOT * HID];               // fc1+gelu output

// ---------------------------------------------------------------------------
// Block-wide sum for 192-thread blocks (6 warps)
// ---------------------------------------------------------------------------
__device__ __forceinline__ float blk_sum192(float v, float* red)
{
    #pragma unroll
    for (int o = 16; o > 0; o >>= 1) v += __shfl_down_sync(0xffffffffu, v, o);
    int lane = threadIdx.x & 31, w = threadIdx.x >> 5;
    if (lane == 0) red[w] = v;
    __syncthreads();
    float s = red[0] + red[1] + red[2] + red[3] + red[4] + red[5];
    __syncthreads();
    return s;
}

// ---------------------------------------------------------------------------
// K1: LN1 + roll(-4,-4) + window partition.  One block per output row.
// ---------------------------------------------------------------------------
__global__ void ln1_partition_kernel(const float* __restrict__ x,
                                     const float* __restrict__ g,
                                     const float* __restrict__ b,
                                     float* __restrict__ out)
{
    __shared__ float red[6];
    int row = blockIdx.x;                    // 0 .. NWIN*NTOK-1
    int c   = threadIdx.x;                   // 0 .. 191
    int win = row >> 6, n = row & 63;
    int bimg = win >> 8;                     // image index
    int wii  = win & 255;
    int wy = wii >> 4, wx = wii & 15;
    int ty = n >> 3,  tx = n & 7;
    int sy = (wy * 8 + ty + SS) & 127;       // un-roll: rolled(-ss) coord
    int sx = (wx * 8 + tx + SS) & 127;
    const float* xr = x + ((size_t)bimg * (HGT * WID) + sy * WID + sx) * CH;

    float v  = xr[c];
    float mu = blk_sum192(v, red) * (1.0f / CH);
    float d  = v - mu;
    float var = blk_sum192(d * d, red) * (1.0f / CH);
    float y  = d * rsqrtf(var + 1e-5f) * g[c] + b[c];
    out[(size_t)row * CH + c] = y;
}

// ---------------------------------------------------------------------------
// Generic tiled fp32 GEMM:  C[M,N] = A[M,K] @ B[K,N] + bias  (+epilogue)
//   EPI = 0: none   1: exact gelu   2: add residual res[M,N]
// BM=BN=64, BK=16, 256 threads, 4x4 micro-tile.
// Requires M%64==0, N%64==0, K%16==0 (true for all our shapes).
// ---------------------------------------------------------------------------
template <int EPI>
__global__ void sgemm_kernel(const float* __restrict__ A,
                             const float* __restrict__ Bm,
                             const float* __restrict__ bias,
                             const float* __restrict__ res,
                             float* __restrict__ Cm,
                             int M, int N, int K)
{
    const int BM = 64, BN = 64, BK = 16;
    __shared__ float As[BK][BM + 1];
    __shared__ float Bs[BK][BN + 1];

    int bm = blockIdx.y * BM;
    int bn = blockIdx.x * BN;
    int tid = threadIdx.x;
    int tx = tid & 15, ty = tid >> 4;

    float acc[4][4] = {};

    for (int k0 = 0; k0 < K; k0 += BK) {
        // A tile 64x16 -> As[k][m]
        {
            int kk = tid & 15;
            int m0 = tid >> 4;
            #pragma unroll
            for (int i = 0; i < 4; i++) {
                int mm = m0 + i * 16;
                As[kk][mm] = A[(size_t)(bm + mm) * K + k0 + kk];
            }
        }
        // B tile 16x64 -> Bs[k][n]
        {
            int nn = tid & 63;
            int k0t = tid >> 6;
            #pragma unroll
            for (int i = 0; i < 4; i++) {
                int kk = k0t + i * 4;
                Bs[kk][nn] = Bm[(size_t)(k0 + kk) * N + bn + nn];
            }
        }
        __syncthreads();
        #pragma unroll
        for (int kk = 0; kk < BK; kk++) {
            float a[4], bb[4];
            #pragma unroll
            for (int i = 0; i < 4; i++) a[i]  = As[kk][ty * 4 + i];
            #pragma unroll
            for (int j = 0; j < 4; j++) bb[j] = Bs[kk][tx * 4 + j];
            #pragma unroll
            for (int i = 0; i < 4; i++)
                #pragma unroll
                for (int j = 0; j < 4; j++)
                    acc[i][j] += a[i] * bb[j];
        }
        __syncthreads();
    }

    #pragma unroll
    for (int i = 0; i < 4; i++) {
        int row = bm + ty * 4 + i;
        #pragma unroll
        for (int j = 0; j < 4; j++) {
            int col = bn + tx * 4 + j;
            float v = acc[i][j] + bias[col];
            if (EPI == 1) v = v * normcdff(v);               // exact gelu
            if (EPI == 2) v += res[(size_t)row * N + col];   // residual
            Cm[(size_t)row * N + col] = v;
        }
    }
}

// ---------------------------------------------------------------------------
// K3: windowed attention.  One block per (window, head); 64 threads = 1/row.
// rel-pos bias + shift mask computed on the fly.
// ---------------------------------------------------------------------------
__global__ void __launch_bounds__(64) attn_kernel(const float* __restrict__ qkv,
                                                  const float* __restrict__ bias_table,
                                                  float* __restrict__ out)
{
    int blk  = blockIdx.x;
    int win  = blk / NHEAD;
    int head = blk % NHEAD;
    int r    = threadIdx.x;                   // query row 0..63

    __shared__ float ks[NTOK][HD + 1];
    __shared__ float vs[NTOK][HD + 1];
    __shared__ float biash[225];
    __shared__ int   regn[NTOK];

    const float* base = qkv + (size_t)win * NTOK * (3 * CH);
    const float  scale = 0.17677669529663687f;    // 32^-0.5

    // q row -> registers (scaled)
    float q[HD];
    {
        const float* qr = base + (size_t)r * (3 * CH) + head * HD;
        #pragma unroll
        for (int d = 0; d < HD; d++) q[d] = qr[d] * scale;
    }
    // k, v rows -> smem
    {
        const float* kr = base + (size_t)r * (3 * CH) + CH     + head * HD;
        const float* vr = base + (size_t)r * (3 * CH) + 2 * CH + head * HD;
        #pragma unroll
        for (int d = 0; d < HD; d++) { ks[r][d] = kr[d]; vs[r][d] = vr[d]; }
    }
    // bias table slice for this head
    for (int i = r; i < 225; i += 64) biash[i] = bias_table[i * NHEAD + head];
    // shift-region id of each token (hp=128, slices [0,120),[120,124),[124,128))
    {
        int wii = win & 255;
        int wy = wii >> 4, wx = wii & 15;
        int ty = r >> 3,  tx = r & 7;
        int y = wy * 8 + ty, x = wx * 8 + tx;
        int ry = (y < 120) ? 0 : (y < 124 ? 1 : 2);
        int rx = (x < 120) ? 0 : (x < 124 ? 1 : 2);
        regn[r] = ry * 3 + rx;
    }
    __syncthreads();

    int ty = r >> 3, tx = r & 7;
    int myreg = regn[r];

    float sc[NTOK];
    #pragma unroll
    for (int j = 0; j < NTOK; j++) {
        float s = 0.0f;
        #pragma unroll
        for (int d = 0; d < HD; d++) s += q[d] * ks[j][d];
        int jy = j >> 3, jx = j & 7;
        int idx = (ty - jy + 7) * 15 + (tx - jx + 7);
        s += biash[idx];
        if (regn[j] != myreg) s -= 100.0f;
        sc[j] = s;
    }

    // softmax over 64 (register-resident)
    float m = -1e30f;
    #pragma unroll
    for (int j = 0; j < NTOK; j++) m = fmaxf(m, sc[j]);
    float sum = 0.0f;
    #pragma unroll
    for (int j = 0; j < NTOK; j++) { sc[j] = expf(sc[j] - m); sum += sc[j]; }
    float inv = 1.0f / sum;

    float acc[HD] = {};
    #pragma unroll
    for (int j = 0; j < NTOK; j++) {
        float p = sc[j];
        #pragma unroll
        for (int d = 0; d < HD; d++) acc[d] += p * vs[j][d];
    }

    float* o = out + ((size_t)win * NTOK + r) * CH + head * HD;
    #pragma unroll
    for (int d = 0; d < HD; d++) o[d] = acc[d] * inv;
}

// ---------------------------------------------------------------------------
// K5: window-reverse + roll(+4,+4) + residual add + LN2.
// One block per token row.
// ---------------------------------------------------------------------------
__global__ void resid_ln2_kernel(const float* __restrict__ x,
                                 const float* __restrict__ proj,
                                 const float* __restrict__ g,
                                 const float* __restrict__ b,
                                 float* __restrict__ x1,
                                 float* __restrict__ ln2out)
{
    __shared__ float red[6];
    int t = blockIdx.x;                       // token index in (B,H*W)
    int c = threadIdx.x;
    int bimg = t / (HGT * WID);
    int pix  = t - bimg * (HGT * WID);
    int y = pix >> 7, x2 = pix & 127;
    int ry = (y  + 128 - SS) & 127;           // position in rolled layout
    int rx = (x2 + 128 - SS) & 127;
    int win = bimg * 256 + (ry >> 3) * 16 + (rx >> 3);
    int n   = ((ry & 7) << 3) | (rx & 7);

    float v = x[(size_t)t * CH + c] + proj[((size_t)win * NTOK + n) * CH + c];
    x1[(size_t)t * CH + c] = v;

    float mu = blk_sum192(v, red) * (1.0f / CH);
    float d  = v - mu;
    float var = blk_sum192(d * d, red) * (1.0f / CH);
    float yv = d * rsqrtf(var + 1e-5f) * g[c] + b[c];
    ln2out[(size_t)t * CH + c] = yv;
}

// ---------------------------------------------------------------------------
// launch
// ---------------------------------------------------------------------------
extern "C" void kernel_launch(void* const* d_in, const int* in_sizes, int n_in,
                              void* d_out, int out_size)
{
    (void)in_sizes; (void)n_in; (void)out_size;
    const float* x     = (const float*)d_in[0];
    // d_in[1], d_in[2] are h, w scalars (fixed 128)
    const float* n1g   = (const float*)d_in[3];
    const float* n1b   = (const float*)d_in[4];
    const float* qkvw  = (const float*)d_in[5];
    const float* qkvb  = (const float*)d_in[6];
    const float* projw = (const float*)d_in[7];
    const float* projb = (const float*)d_in[8];
    const float* rbt   = (const float*)d_in[9];
    const float* n2g   = (const float*)d_in[10];
    const float* n2b   = (const float*)d_in[11];
    const float* fc1w  = (const float*)d_in[12];
    const float* fc1b  = (const float*)d_in[13];
    const float* fc2w  = (const float*)d_in[14];
    const float* fc2b  = (const float*)d_in[15];
    float* out = (float*)d_out;

    float *xw, *qkv, *attn, *proj, *x1, *ln2, *h1;
    cudaGetSymbolAddress((void**)&xw,   g_xw);
    cudaGetSymbolAddress((void**)&qkv,  g_qkv);
    cudaGetSymbolAddress((void**)&attn, g_attn);
    cudaGetSymbolAddress((void**)&proj, g_proj);
    cudaGetSymbolAddress((void**)&x1,   g_x1);
    cudaGetSymbolAddress((void**)&ln2,  g_ln2);
    cudaGetSymbolAddress((void**)&h1,   g_h1);

    // 1. LN1 + shift + window partition
    ln1_partition_kernel<<<TOT, CH>>>(x, n1g, n1b, xw);

    // 2. qkv GEMM: (131072 x 192) @ (192 x 576)
    sgemm_kernel<0><<<dim3(576 / 64, TOT / 64), 256>>>(xw, qkvw, qkvb, nullptr, qkv,
                                                       TOT, 3 * CH, CH);

    // 3. windowed attention
    attn_kernel<<<NWIN * NHEAD, 64>>>(qkv, rbt, attn);

    // 4. proj GEMM: (131072 x 192) @ (192 x 192)
    sgemm_kernel<0><<<dim3(CH / 64, TOT / 64), 256>>>(attn, projw, projb, nullptr, proj,
                                                      TOT, CH, CH);

    // 5. reverse + roll + residual + LN2
    resid_ln2_kernel<<<TOT, CH>>>(x, proj, n2g, n2b, x1, ln2);

    // 6. fc1 GEMM + exact gelu: (131072 x 192) @ (192 x 768)
    sgemm_kernel<1><<<dim3(HID / 64, TOT / 64), 256>>>(ln2, fc1w, fc1b, nullptr, h1,
                                                       TOT, HID, CH);

    // 7. fc2 GEMM + residual: (131072 x 768) @ (768 x 192) + x1
    sgemm_kernel<2><<<dim3(CH / 64, TOT / 64), 256>>>(h1, fc2w, fc2b, x1, out,
                                                      TOT, CH, HID);
}

// round 3
// speedup vs baseline: 3.1648x; 3.1648x over previous
#include <cuda_runtime.h>
#include <cuda_bf16.h>
#include <math.h>
#include <stdint.h>

// ---------------------------------------------------------------------------
// Problem constants (fixed by setup_inputs)
// ---------------------------------------------------------------------------
#define BATCH 8
#define HGT   128
#define WID   128
#define CH    192
#define NHEAD 6
#define HD    32
#define WS    8
#define SS    4
#define NTOK  64
#define NWIN  (BATCH * 16 * 16)       // 2048
#define TOT   (BATCH * HGT * WID)     // 131072
#define HID   (CH * 4)                // 768

typedef __nv_bfloat16 bf16;

// ---------------------------------------------------------------------------
// Scratch (static device globals; allocation-free)
// ---------------------------------------------------------------------------
__device__ bf16  g_xw  [(size_t)TOT * CH];          // LN1 + shift + partition (bf16)
__device__ float g_qkv [(size_t)TOT * 3 * CH];      // qkv (fp32 for attention)
__device__ bf16  g_attn[(size_t)TOT * CH];          // attention out (bf16)
__device__ float g_proj[(size_t)TOT * CH];          // proj out (fp32)
__device__ float g_x1  [(size_t)TOT * CH];          // residual 1 (fp32)
__device__ bf16  g_ln2 [(size_t)TOT * CH];          // LN2 out (bf16)
__device__ bf16  g_h1  [(size_t)TOT * HID];         // fc1+gelu out (bf16)
// transposed bf16 weights: Wt[n][k]
__device__ bf16  g_wqkv [3 * CH * CH];
__device__ bf16  g_wproj[CH * CH];
__device__ bf16  g_wfc1 [HID * CH];
__device__ bf16  g_wfc2 [CH * HID];

// ---------------------------------------------------------------------------
// helpers
// ---------------------------------------------------------------------------
__device__ __forceinline__ uint32_t smem_u32(const void* p) {
    uint32_t a;
    asm("{ .reg .u64 t; cvta.to.shared.u64 t, %1; cvt.u32.u64 %0, t; }" : "=r"(a) : "l"(p));
    return a;
}

__device__ __forceinline__ float blk_sum192(float v, float* red) {
    #pragma unroll
    for (int o = 16; o > 0; o >>= 1) v += __shfl_down_sync(0xffffffffu, v, o);
    int lane = threadIdx.x & 31, w = threadIdx.x >> 5;
    if (lane == 0) red[w] = v;
    __syncthreads();
    float s = red[0] + red[1] + red[2] + red[3] + red[4] + red[5];
    __syncthreads();
    return s;
}

// ---------------------------------------------------------------------------
// Weight transpose + convert: Wt[n*K+k] = bf16(W[k*N+n])
// ---------------------------------------------------------------------------
__global__ void wconv_kernel(const float* __restrict__ W, bf16* __restrict__ Wt,
                             int K, int N) {
    int i = blockIdx.x * 256 + threadIdx.x;
    if (i < K * N) {
        int n = i / K, k = i - n * K;
        Wt[i] = __float2bfloat16(W[(size_t)k * N + n]);
    }
}

// ---------------------------------------------------------------------------
// K1: LN1 + roll(-4,-4) + window partition -> bf16
// ---------------------------------------------------------------------------
__global__ void ln1_partition_kernel(const float* __restrict__ x,
                                     const float* __restrict__ g,
                                     const float* __restrict__ b,
                                     bf16* __restrict__ out) {
    __shared__ float red[6];
    int row = blockIdx.x;
    int c   = threadIdx.x;
    int win = row >> 6, n = row & 63;
    int bimg = win >> 8;
    int wii  = win & 255;
    int wy = wii >> 4, wx = wii & 15;
    int ty = n >> 3,  tx = n & 7;
    int sy = (wy * 8 + ty + SS) & 127;
    int sx = (wx * 8 + tx + SS) & 127;
    const float* xr = x + ((size_t)bimg * (HGT * WID) + sy * WID + sx) * CH;

    float v  = xr[c];
    float mu = blk_sum192(v, red) * (1.0f / CH);
    float d  = v - mu;
    float var = blk_sum192(d * d, red) * (1.0f / CH);
    float y  = d * rsqrtf(var + 1e-5f) * g[c] + b[c];
    out[(size_t)row * CH + c] = __float2bfloat16(y);
}

// ---------------------------------------------------------------------------
// HMMA GEMM (mma.sync bf16):  C[M,Nbig] = A[M,Kbig] @ Wt^T + bias (+epi)
// Wt is [Nbig][Kbig] (n-major).  BM=128, BN=64, BK=32, 256 thr, warp 32x32.
// EPI 0: +bias -> fp32    1: +bias,gelu -> bf16    2: +bias + res -> fp32
// ---------------------------------------------------------------------------
#define AROW_B 80                    // padded row pitch in bytes (32 bf16 + 8 pad)
#define A_STAGE_B (128 * AROW_B)     // 10240
#define B_STAGE_B (64 * AROW_B)      // 5120
#define STAGE_B   (A_STAGE_B + B_STAGE_B)

__device__ __forceinline__ void cpasync16(uint32_t so, const void* g) {
    asm volatile("cp.async.cg.shared.global [%0], [%1], 16;"
                 :: "r"(so), "l"(__cvta_generic_to_global(g)) : "memory");
}

__device__ __forceinline__ void load_stage(uint32_t sA, uint32_t sB,
                                           const bf16* Ag, const bf16* Bg,
                                           int Kbig, int tid) {
    // A: 128 rows x 4 segments of 16B
    #pragma unroll
    for (int i = 0; i < 2; i++) {
        int t = tid + i * 256;
        int row = t >> 2, seg = t & 3;
        cpasync16(sA + row * AROW_B + seg * 16, Ag + (size_t)row * Kbig + seg * 8);
    }
    // B: 64 rows x 4 segments
    {
        int row = tid >> 2, seg = tid & 3;
        cpasync16(sB + row * AROW_B + seg * 16, Bg + (size_t)row * Kbig + seg * 8);
    }
}

template <int EPI>
__global__ void __launch_bounds__(256) hgemm(const bf16* __restrict__ A,
                                             const bf16* __restrict__ Bt,
                                             const float* __restrict__ bias,
                                             const float* __restrict__ res,
                                             void* __restrict__ Cout,
                                             int Kbig, int Nbig) {
    __shared__ __align__(128) char smem[2 * STAGE_B];
    __shared__ float sbias[64];

    const int tid  = threadIdx.x;
    const int lane = tid & 31;
    const int w    = tid >> 5;
    const int bm   = blockIdx.y * 128;
    const int bn   = blockIdx.x * 64;
    const int wm   = (w & 3) * 32;       // warp m offset within tile
    const int wn   = (w >> 2) * 32;      // warp n offset within tile

    const uint32_t sb = smem_u32(smem);
    if (tid < 64) sbias[tid] = bias[bn + tid];

    const bf16* Ag = A  + (size_t)bm * Kbig;
    const bf16* Bg = Bt + (size_t)bn * Kbig;
    const int NC = Kbig >> 5;            // BK = 32

    // per-lane ldmatrix offsets
    const int aRow = (lane & 7) + ((lane >> 3) & 1) * 8;   // within m16
    const int aCol = (lane >> 4) * 8;                      // k segment
    const int bRow = (lane & 7) + (lane >> 4) * 8;         // within n16
    const int bCol = ((lane >> 3) & 1) * 8;                // k segment

    float acc[2][4][4];
    #pragma unroll
    for (int i = 0; i < 2; i++)
        #pragma unroll
        for (int j = 0; j < 4; j++)
            #pragma unroll
            for (int k = 0; k < 4; k++) acc[i][j][k] = 0.0f;

    load_stage(sb, sb + A_STAGE_B, Ag, Bg, Kbig, tid);
    asm volatile("cp.async.commit_group;" ::: "memory");

    for (int c = 0; c < NC; c++) {
        if (c + 1 < NC) {
            uint32_t nbuf = sb + ((c + 1) & 1) * STAGE_B;
            load_stage(nbuf, nbuf + A_STAGE_B,
                       Ag + (size_t)(c + 1) * 32, Bg + (size_t)(c + 1) * 32, Kbig, tid);
            asm volatile("cp.async.commit_group;" ::: "memory");
            asm volatile("cp.async.wait_group 1;" ::: "memory");
        } else {
            asm volatile("cp.async.wait_group 0;" ::: "memory");
        }
        __syncthreads();

        uint32_t cA = sb + (c & 1) * STAGE_B;
        uint32_t cB = cA + A_STAGE_B;

        #pragma unroll
        for (int ks = 0; ks < 2; ks++) {
            uint32_t a0[4], a1[4], b0[4], b1[4];
            uint32_t addrA0 = cA + (wm + 0  + aRow) * AROW_B + (ks * 16 + aCol) * 2;
            uint32_t addrA1 = cA + (wm + 16 + aRow) * AROW_B + (ks * 16 + aCol) * 2;
            uint32_t addrB0 = cB + (wn + 0  + bRow) * AROW_B + (ks * 16 + bCol) * 2;
            uint32_t addrB1 = cB + (wn + 16 + bRow) * AROW_B + (ks * 16 + bCol) * 2;
            asm volatile("ldmatrix.sync.aligned.m8n8.x4.shared.b16 {%0,%1,%2,%3}, [%4];"
                         : "=r"(a0[0]), "=r"(a0[1]), "=r"(a0[2]), "=r"(a0[3]) : "r"(addrA0));
            asm volatile("ldmatrix.sync.aligned.m8n8.x4.shared.b16 {%0,%1,%2,%3}, [%4];"
                         : "=r"(a1[0]), "=r"(a1[1]), "=r"(a1[2]), "=r"(a1[3]) : "r"(addrA1));
            asm volatile("ldmatrix.sync.aligned.m8n8.x4.shared.b16 {%0,%1,%2,%3}, [%4];"
                         : "=r"(b0[0]), "=r"(b0[1]), "=r"(b0[2]), "=r"(b0[3]) : "r"(addrB0));
            asm volatile("ldmatrix.sync.aligned.m8n8.x4.shared.b16 {%0,%1,%2,%3}, [%4];"
                         : "=r"(b1[0]), "=r"(b1[1]), "=r"(b1[2]), "=r"(b1[3]) : "r"(addrB1));

            const uint32_t* am[2] = { a0, a1 };
            const uint32_t* bp[4] = { b0, b0 + 2, b1, b1 + 2 };
            #pragma unroll
            for (int mi = 0; mi < 2; mi++)
                #pragma unroll
                for (int ni = 0; ni < 4; ni++) {
                    float* d = acc[mi][ni];
                    asm volatile(
                        "mma.sync.aligned.m16n8k16.row.col.f32.bf16.bf16.f32 "
                        "{%0,%1,%2,%3}, {%4,%5,%6,%7}, {%8,%9}, {%0,%1,%2,%3};"
                        : "+f"(d[0]), "+f"(d[1]), "+f"(d[2]), "+f"(d[3])
                        : "r"(am[mi][0]), "r"(am[mi][1]), "r"(am[mi][2]), "r"(am[mi][3]),
                          "r"(bp[ni][0]), "r"(bp[ni][1]));
                }
        }
        __syncthreads();
    }

    // epilogue
    const int g = lane >> 2, t4 = lane & 3;
    #pragma unroll
    for (int mi = 0; mi < 2; mi++) {
        #pragma unroll
        for (int ni = 0; ni < 4; ni++) {
            int colL = wn + ni * 8 + t4 * 2;          // local col (pair)
            int col  = bn + colL;
            size_t row0 = (size_t)(bm + wm + mi * 16 + g);
            size_t row1 = row0 + 8;
            float v00 = acc[mi][ni][0] + sbias[colL];
            float v01 = acc[mi][ni][1] + sbias[colL + 1];
            float v10 = acc[mi][ni][2] + sbias[colL];
            float v11 = acc[mi][ni][3] + sbias[colL + 1];
            if (EPI == 0) {
                float* C = (float*)Cout;
                *(float2*)(C + row0 * Nbig + col) = make_float2(v00, v01);
                *(float2*)(C + row1 * Nbig + col) = make_float2(v10, v11);
            } else if (EPI == 1) {
                v00 = v00 * normcdff(v00); v01 = v01 * normcdff(v01);
                v10 = v10 * normcdff(v10); v11 = v11 * normcdff(v11);
                bf16* C = (bf16*)Cout;
                *(__nv_bfloat162*)(C + row0 * Nbig + col) = __floats2bfloat162_rn(v00, v01);
                *(__nv_bfloat162*)(C + row1 * Nbig + col) = __floats2bfloat162_rn(v10, v11);
            } else {
                float2 r0 = *(const float2*)(res + row0 * Nbig + col);
                float2 r1 = *(const float2*)(res + row1 * Nbig + col);
                float* C = (float*)Cout;
                *(float2*)(C + row0 * Nbig + col) = make_float2(v00 + r0.x, v01 + r0.y);
                *(float2*)(C + row1 * Nbig + col) = make_float2(v10 + r1.x, v11 + r1.y);
            }
        }
    }
}

// ---------------------------------------------------------------------------
// K3: windowed attention (fp32 in, bf16 out)
// ---------------------------------------------------------------------------
__global__ void __launch_bounds__(64) attn_kernel(const float* __restrict__ qkv,
                                                  const float* __restrict__ bias_table,
                                                  bf16* __restrict__ out) {
    int blk  = blockIdx.x;
    int win  = blk / NHEAD;
    int head = blk % NHEAD;
    int r    = threadIdx.x;

    __shared__ float ks[NTOK][HD + 1];
    __shared__ float vs[NTOK][HD + 1];
    __shared__ float biash[225];
    __shared__ int   regn[NTOK];

    const float* base = qkv + (size_t)win * NTOK * (3 * CH);
    const float  scale = 0.17677669529663687f;

    float q[HD];
    {
        const float* qr = base + (size_t)r * (3 * CH) + head * HD;
        #pragma unroll
        for (int d = 0; d < HD; d++) q[d] = qr[d] * scale;
    }
    {
        const float* kr = base + (size_t)r * (3 * CH) + CH     + head * HD;
        const float* vr = base + (size_t)r * (3 * CH) + 2 * CH + head * HD;
        #pragma unroll
        for (int d = 0; d < HD; d++) { ks[r][d] = kr[d]; vs[r][d] = vr[d]; }
    }
    for (int i = r; i < 225; i += 64) biash[i] = bias_table[i * NHEAD + head];
    {
        int wii = win & 255;
        int wy = wii >> 4, wx = wii & 15;
        int ty = r >> 3,  tx = r & 7;
        int y = wy * 8 + ty, x = wx * 8 + tx;
        int ry = (y < 120) ? 0 : (y < 124 ? 1 : 2);
        int rx = (x < 120) ? 0 : (x < 124 ? 1 : 2);
        regn[r] = ry * 3 + rx;
    }
    __syncthreads();

    int ty = r >> 3, tx = r & 7;
    int myreg = regn[r];

    float sc[NTOK];
    #pragma unroll
    for (int j = 0; j < NTOK; j++) {
        float s = 0.0f;
        #pragma unroll
        for (int d = 0; d < HD; d++) s += q[d] * ks[j][d];
        int jy = j >> 3, jx = j & 7;
        s += biash[(ty - jy + 7) * 15 + (tx - jx + 7)];
        if (regn[j] != myreg) s -= 100.0f;
        sc[j] = s;
    }

    float m = -1e30f;
    #pragma unroll
    for (int j = 0; j < NTOK; j++) m = fmaxf(m, sc[j]);
    float sum = 0.0f;
    #pragma unroll
    for (int j = 0; j < NTOK; j++) { sc[j] = expf(sc[j] - m); sum += sc[j]; }
    float inv = 1.0f / sum;

    float acc[HD] = {};
    #pragma unroll
    for (int j = 0; j < NTOK; j++) {
        float p = sc[j];
        #pragma unroll
        for (int d = 0; d < HD; d++) acc[d] += p * vs[j][d];
    }

    bf16* o = out + ((size_t)win * NTOK + r) * CH + head * HD;
    #pragma unroll
    for (int d = 0; d < HD; d++) o[d] = __float2bfloat16(acc[d] * inv);
}

// ---------------------------------------------------------------------------
// K5: window-reverse + roll + residual + LN2 (x1 fp32, ln2 bf16)
// ---------------------------------------------------------------------------
__global__ void resid_ln2_kernel(const float* __restrict__ x,
                                 const float* __restrict__ proj,
                                 const float* __restrict__ g,
                                 const float* __restrict__ b,
                                 float* __restrict__ x1,
                                 bf16* __restrict__ ln2out) {
    __shared__ float red[6];
    int t = blockIdx.x;
    int c = threadIdx.x;
    int bimg = t / (HGT * WID);
    int pix  = t - bimg * (HGT * WID);
    int y = pix >> 7, x2 = pix & 127;
    int ry = (y  + 128 - SS) & 127;
    int rx = (x2 + 128 - SS) & 127;
    int win = bimg * 256 + (ry >> 3) * 16 + (rx >> 3);
    int n   = ((ry & 7) << 3) | (rx & 7);

    float v = x[(size_t)t * CH + c] + proj[((size_t)win * NTOK + n) * CH + c];
    x1[(size_t)t * CH + c] = v;

    float mu = blk_sum192(v, red) * (1.0f / CH);
    float d  = v - mu;
    float var = blk_sum192(d * d, red) * (1.0f / CH);
    float yv = d * rsqrtf(var + 1e-5f) * g[c] + b[c];
    ln2out[(size_t)t * CH + c] = __float2bfloat16(yv);
}

// ---------------------------------------------------------------------------
// launch
// ---------------------------------------------------------------------------
extern "C" void kernel_launch(void* const* d_in, const int* in_sizes, int n_in,
                              void* d_out, int out_size) {
    (void)in_sizes; (void)n_in; (void)out_size;
    const float* x     = (const float*)d_in[0];
    const float* n1g   = (const float*)d_in[3];
    const float* n1b   = (const float*)d_in[4];
    const float* qkvw  = (const float*)d_in[5];
    const float* qkvb  = (const float*)d_in[6];
    const float* projw = (const float*)d_in[7];
    const float* projb = (const float*)d_in[8];
    const float* rbt   = (const float*)d_in[9];
    const float* n2g   = (const float*)d_in[10];
    const float* n2b   = (const float*)d_in[11];
    const float* fc1w  = (const float*)d_in[12];
    const float* fc1b  = (const float*)d_in[13];
    const float* fc2w  = (const float*)d_in[14];
    const float* fc2b  = (const float*)d_in[15];
    float* out = (float*)d_out;

    bf16 *xw, *attnb, *ln2, *h1, *wqkv, *wproj, *wfc1, *wfc2;
    float *qkv, *proj, *x1;
    cudaGetSymbolAddress((void**)&xw,    g_xw);
    cudaGetSymbolAddress((void**)&qkv,   g_qkv);
    cudaGetSymbolAddress((void**)&attnb, g_attn);
    cudaGetSymbolAddress((void**)&proj,  g_proj);
    cudaGetSymbolAddress((void**)&x1,    g_x1);
    cudaGetSymbolAddress((void**)&ln2,   g_ln2);
    cudaGetSymbolAddress((void**)&h1,    g_h1);
    cudaGetSymbolAddress((void**)&wqkv,  g_wqkv);
    cudaGetSymbolAddress((void**)&wproj, g_wproj);
    cudaGetSymbolAddress((void**)&wfc1,  g_wfc1);
    cudaGetSymbolAddress((void**)&wfc2,  g_wfc2);

    // weight transpose+convert (tiny)
    wconv_kernel<<<(3 * CH * CH + 255) / 256, 256>>>(qkvw, wqkv, CH, 3 * CH);
    wconv_kernel<<<(CH * CH + 255) / 256, 256>>>(projw, wproj, CH, CH);
    wconv_kernel<<<(HID * CH + 255) / 256, 256>>>(fc1w, wfc1, CH, HID);
    wconv_kernel<<<(CH * HID + 255) / 256, 256>>>(fc2w, wfc2, HID, CH);

    // 1. LN1 + shift + window partition (bf16)
    ln1_partition_kernel<<<TOT, CH>>>(x, n1g, n1b, xw);

    // 2. qkv: (131072 x 192) @ (192 x 576) -> fp32
    hgemm<0><<<dim3(576 / 64, TOT / 128), 256>>>(xw, wqkv, qkvb, nullptr, qkv, CH, 3 * CH);

    // 3. attention -> bf16
    attn_kernel<<<NWIN * NHEAD, 64>>>(qkv, rbt, attnb);

    // 4. proj: (131072 x 192) @ (192 x 192) -> fp32
    hgemm<0><<<dim3(CH / 64, TOT / 128), 256>>>(attnb, wproj, projb, nullptr, proj, CH, CH);

    // 5. reverse + roll + residual + LN2
    resid_ln2_kernel<<<TOT, CH>>>(x, proj, n2g, n2b, x1, ln2);

    // 6. fc1 + gelu: (131072 x 192) @ (192 x 768) -> bf16
    hgemm<1><<<dim3(HID / 64, TOT / 128), 256>>>(ln2, wfc1, fc1b, nullptr, h1, CH, HID);

    // 7. fc2 + residual: (131072 x 768) @ (768 x 192) + x1 -> out
    hgemm<2><<<dim3(CH / 64, TOT / 128), 256>>>(h1, wfc2, fc2b, x1, out, HID, CH);
}

// round 4
// speedup vs baseline: 6.0707x; 1.9182x over previous
#include <cuda_runtime.h>
#include <cuda_bf16.h>
#include <math.h>
#include <stdint.h>

// ---------------------------------------------------------------------------
// Problem constants
// ---------------------------------------------------------------------------
#define BATCH 8
#define HGT   128
#define WID   128
#define CH    192
#define NHEAD 6
#define HD    32
#define WS    8
#define SS    4
#define NTOK  64
#define NWIN  (BATCH * 16 * 16)       // 2048
#define TOT   (BATCH * HGT * WID)     // 131072
#define HID   (CH * 4)                // 768
#define QSCALE 0.17677669529663687f   // 32^-0.5

typedef __nv_bfloat16 bf16;

// ---------------------------------------------------------------------------
// Scratch (static device globals; allocation-free)
// ---------------------------------------------------------------------------
__device__ __align__(256) bf16  g_xw  [(size_t)TOT * CH];       // LN1+shift+partition
__device__ __align__(256) bf16  g_qkvb[(size_t)TOT * 3 * CH];   // qkv bf16 (q pre-scaled)
__device__ __align__(256) bf16  g_attn[(size_t)TOT * CH];       // attention out
__device__ __align__(256) float g_x1  [(size_t)TOT * CH];       // x + proj (token order)
__device__ __align__(256) bf16  g_ln2 [(size_t)TOT * CH];       // LN2 out
__device__ __align__(256) bf16  g_h1  [(size_t)TOT * HID];      // fc1+gelu out
__device__ __align__(256) bf16  g_wqkv [3 * CH * CH];
__device__ __align__(256) bf16  g_wproj[CH * CH];
__device__ __align__(256) bf16  g_wfc1 [HID * CH];
__device__ __align__(256) bf16  g_wfc2 [CH * HID];

// ---------------------------------------------------------------------------
// helpers
// ---------------------------------------------------------------------------
__device__ __forceinline__ uint32_t smem_u32(const void* p) {
    uint32_t a;
    asm("{ .reg .u64 t; cvta.to.shared.u64 t, %1; cvt.u32.u64 %0, t; }" : "=r"(a) : "l"(p));
    return a;
}
__device__ __forceinline__ void cpasync16(uint32_t so, const void* g) {
    asm volatile("cp.async.cg.shared.global [%0], [%1], 16;"
                 :: "r"(so), "l"(__cvta_generic_to_global(g)) : "memory");
}
__device__ __forceinline__ void ldm_x4(uint32_t* r, uint32_t addr) {
    asm volatile("ldmatrix.sync.aligned.m8n8.x4.shared.b16 {%0,%1,%2,%3}, [%4];"
                 : "=r"(r[0]), "=r"(r[1]), "=r"(r[2]), "=r"(r[3]) : "r"(addr));
}
__device__ __forceinline__ void ldm_x4t(uint32_t* r, uint32_t addr) {
    asm volatile("ldmatrix.sync.aligned.m8n8.x4.trans.shared.b16 {%0,%1,%2,%3}, [%4];"
                 : "=r"(r[0]), "=r"(r[1]), "=r"(r[2]), "=r"(r[3]) : "r"(addr));
}
__device__ __forceinline__ void mma16816(float* d, const uint32_t* a, const uint32_t* b) {
    asm volatile("mma.sync.aligned.m16n8k16.row.col.f32.bf16.bf16.f32 "
                 "{%0,%1,%2,%3}, {%4,%5,%6,%7}, {%8,%9}, {%0,%1,%2,%3};"
                 : "+f"(d[0]), "+f"(d[1]), "+f"(d[2]), "+f"(d[3])
                 : "r"(a[0]), "r"(a[1]), "r"(a[2]), "r"(a[3]), "r"(b[0]), "r"(b[1]));
}
__device__ __forceinline__ uint32_t packbf(float a, float b) {
    __nv_bfloat162 t = __floats2bfloat162_rn(a, b);
    return *(uint32_t*)&t;
}

// ---------------------------------------------------------------------------
// Weight transpose + convert: Wt[n*K+k] = bf16(W[k*N+n])
// ---------------------------------------------------------------------------
__global__ void wconv_kernel(const float* __restrict__ W, bf16* __restrict__ Wt,
                             int K, int N) {
    int i = blockIdx.x * 256 + threadIdx.x;
    if (i < K * N) {
        int n = i / K, k = i - n * K;
        Wt[i] = __float2bfloat16(W[(size_t)k * N + n]);
    }
}

// ---------------------------------------------------------------------------
// K1: LN1 + roll(-4,-4) + window partition -> bf16.  Warp per row.
// ---------------------------------------------------------------------------
__global__ void __launch_bounds__(256) ln1_kernel(const float* __restrict__ x,
                                                  const float* __restrict__ g,
                                                  const float* __restrict__ b,
                                                  bf16* __restrict__ out) {
    int row  = blockIdx.x * 8 + (threadIdx.x >> 5);  // window-layout row
    int lane = threadIdx.x & 31;
    int win = row >> 6, n = row & 63;
    int bimg = win >> 8;
    int wii  = win & 255;
    int wy = wii >> 4, wx = wii & 15;
    int sy = (wy * 8 + (n >> 3) + SS) & 127;
    int sx = (wx * 8 + (n & 7) + SS) & 127;
    const float* xr = x + ((size_t)bimg * (HGT * WID) + sy * WID + sx) * CH;

    float v[6];
    #pragma unroll
    for (int i = 0; i < 6; i++) v[i] = xr[lane + 32 * i];
    float s = v[0] + v[1] + v[2] + v[3] + v[4] + v[5];
    #pragma unroll
    for (int o = 16; o > 0; o >>= 1) s += __shfl_xor_sync(~0u, s, o);
    float mu = s * (1.0f / CH);
    float q = 0.f;
    #pragma unroll
    for (int i = 0; i < 6; i++) { v[i] -= mu; q += v[i] * v[i]; }
    #pragma unroll
    for (int o = 16; o > 0; o >>= 1) q += __shfl_xor_sync(~0u, q, o);
    float rs = rsqrtf(q * (1.0f / CH) + 1e-5f);
    bf16* orow = out + (size_t)row * CH;
    #pragma unroll
    for (int i = 0; i < 6; i++) {
        int c = lane + 32 * i;
        orow[c] = __float2bfloat16(v[i] * rs * g[c] + b[c]);
    }
}

// ---------------------------------------------------------------------------
// K5b: LN2 only (token order).  Warp per row.
// ---------------------------------------------------------------------------
__global__ void __launch_bounds__(256) ln2_kernel(const float* __restrict__ x1,
                                                  const float* __restrict__ g,
                                                  const float* __restrict__ b,
                                                  bf16* __restrict__ out) {
    int row  = blockIdx.x * 8 + (threadIdx.x >> 5);
    int lane = threadIdx.x & 31;
    const float* xr = x1 + (size_t)row * CH;
    float v[6];
    #pragma unroll
    for (int i = 0; i < 6; i++) v[i] = xr[lane + 32 * i];
    float s = v[0] + v[1] + v[2] + v[3] + v[4] + v[5];
    #pragma unroll
    for (int o = 16; o > 0; o >>= 1) s += __shfl_xor_sync(~0u, s, o);
    float mu = s * (1.0f / CH);
    float q = 0.f;
    #pragma unroll
    for (int i = 0; i < 6; i++) { v[i] -= mu; q += v[i] * v[i]; }
    #pragma unroll
    for (int o = 16; o > 0; o >>= 1) q += __shfl_xor_sync(~0u, q, o);
    float rs = rsqrtf(q * (1.0f / CH) + 1e-5f);
    bf16* orow = out + (size_t)row * CH;
    #pragma unroll
    for (int i = 0; i < 6; i++) {
        int c = lane + 32 * i;
        orow[c] = __float2bfloat16(v[i] * rs * g[c] + b[c]);
    }
}

// ---------------------------------------------------------------------------
// HMMA GEMM: C[M,Nbig] = A[M,Kbig] @ Wt^T + bias (+epi).  BM=128 BN=64 BK=32.
// EPI 1: gelu->bf16   2: +res->fp32   3: qkv bf16 (scale q cols)   4: proj permute+res->x1
// ---------------------------------------------------------------------------
#define AROW_B 80
#define A_STAGE_B (128 * AROW_B)
#define B_STAGE_B (64 * AROW_B)
#define STAGE_B   (A_STAGE_B + B_STAGE_B)

__device__ __forceinline__ void load_stage(uint32_t sA, uint32_t sB,
                                           const bf16* Ag, const bf16* Bg,
                                           int Kbig, int tid) {
    #pragma unroll
    for (int i = 0; i < 2; i++) {
        int t = tid + i * 256;
        int row = t >> 2, seg = t & 3;
        cpasync16(sA + row * AROW_B + seg * 16, Ag + (size_t)row * Kbig + seg * 8);
    }
    {
        int row = tid >> 2, seg = tid & 3;
        cpasync16(sB + row * AROW_B + seg * 16, Bg + (size_t)row * Kbig + seg * 8);
    }
}

// window-layout row -> token index (reverse partition + roll(+4,+4))
__device__ __forceinline__ int row2tok(int row) {
    int win = row >> 6, n = row & 63;
    int bimg = win >> 8;
    int wii  = win & 255;
    int ry = (wii >> 4) * 8 + (n >> 3);
    int rx = (wii & 15) * 8 + (n & 7);
    int y = (ry + SS) & 127;
    int x = (rx + SS) & 127;
    return bimg * (HGT * WID) + y * WID + x;
}

template <int EPI>
__global__ void __launch_bounds__(256) hgemm(const bf16* __restrict__ A,
                                             const bf16* __restrict__ Bt,
                                             const float* __restrict__ bias,
                                             const float* __restrict__ res,
                                             void* __restrict__ Cout,
                                             int Kbig, int Nbig) {
    __shared__ __align__(128) char smem[2 * STAGE_B];
    __shared__ float sbias[64];

    const int tid  = threadIdx.x;
    const int lane = tid & 31;
    const int w    = tid >> 5;
    const int bm   = blockIdx.y * 128;
    const int bn   = blockIdx.x * 64;
    const int wm   = (w & 3) * 32;
    const int wn   = (w >> 2) * 32;

    const uint32_t sb = smem_u32(smem);
    if (tid < 64) sbias[tid] = bias[bn + tid];

    const bf16* Ag = A  + (size_t)bm * Kbig;
    const bf16* Bg = Bt + (size_t)bn * Kbig;
    const int NC = Kbig >> 5;

    const int aRow = (lane & 7) + ((lane >> 3) & 1) * 8;
    const int aCol = (lane >> 4) * 8;
    const int bRow = (lane & 7) + (lane >> 4) * 8;
    const int bCol = ((lane >> 3) & 1) * 8;

    float acc[2][4][4];
    #pragma unroll
    for (int i = 0; i < 2; i++)
        #pragma unroll
        for (int j = 0; j < 4; j++)
            #pragma unroll
            for (int k = 0; k < 4; k++) acc[i][j][k] = 0.0f;

    load_stage(sb, sb + A_STAGE_B, Ag, Bg, Kbig, tid);
    asm volatile("cp.async.commit_group;" ::: "memory");

    for (int c = 0; c < NC; c++) {
        if (c + 1 < NC) {
            uint32_t nbuf = sb + ((c + 1) & 1) * STAGE_B;
            load_stage(nbuf, nbuf + A_STAGE_B,
                       Ag + (size_t)(c + 1) * 32, Bg + (size_t)(c + 1) * 32, Kbig, tid);
            asm volatile("cp.async.commit_group;" ::: "memory");
            asm volatile("cp.async.wait_group 1;" ::: "memory");
        } else {
            asm volatile("cp.async.wait_group 0;" ::: "memory");
        }
        __syncthreads();

        uint32_t cA = sb + (c & 1) * STAGE_B;
        uint32_t cB = cA + A_STAGE_B;

        #pragma unroll
        for (int ks = 0; ks < 2; ks++) {
            uint32_t a0[4], a1[4], b0[4], b1[4];
            ldm_x4(a0, cA + (wm + 0  + aRow) * AROW_B + (ks * 16 + aCol) * 2);
            ldm_x4(a1, cA + (wm + 16 + aRow) * AROW_B + (ks * 16 + aCol) * 2);
            ldm_x4(b0, cB + (wn + 0  + bRow) * AROW_B + (ks * 16 + bCol) * 2);
            ldm_x4(b1, cB + (wn + 16 + bRow) * AROW_B + (ks * 16 + bCol) * 2);
            const uint32_t* am[2] = { a0, a1 };
            const uint32_t* bp[4] = { b0, b0 + 2, b1, b1 + 2 };
            #pragma unroll
            for (int mi = 0; mi < 2; mi++)
                #pragma unroll
                for (int ni = 0; ni < 4; ni++)
                    mma16816(acc[mi][ni], am[mi], bp[ni]);
        }
        __syncthreads();
    }

    const int g = lane >> 2, t4 = lane & 3;
    #pragma unroll
    for (int mi = 0; mi < 2; mi++) {
        #pragma unroll
        for (int ni = 0; ni < 4; ni++) {
            int colL = wn + ni * 8 + t4 * 2;
            int col  = bn + colL;
            int row0 = bm + wm + mi * 16 + g;
            int row1 = row0 + 8;
            float v00 = acc[mi][ni][0] + sbias[colL];
            float v01 = acc[mi][ni][1] + sbias[colL + 1];
            float v10 = acc[mi][ni][2] + sbias[colL];
            float v11 = acc[mi][ni][3] + sbias[colL + 1];
            if (EPI == 1) {
                v00 = v00 * normcdff(v00); v01 = v01 * normcdff(v01);
                v10 = v10 * normcdff(v10); v11 = v11 * normcdff(v11);
                bf16* C = (bf16*)Cout;
                *(__nv_bfloat162*)(C + (size_t)row0 * Nbig + col) = __floats2bfloat162_rn(v00, v01);
                *(__nv_bfloat162*)(C + (size_t)row1 * Nbig + col) = __floats2bfloat162_rn(v10, v11);
            } else if (EPI == 2) {
                float2 r0 = *(const float2*)(res + (size_t)row0 * Nbig + col);
                float2 r1 = *(const float2*)(res + (size_t)row1 * Nbig + col);
                float* C = (float*)Cout;
                *(float2*)(C + (size_t)row0 * Nbig + col) = make_float2(v00 + r0.x, v01 + r0.y);
                *(float2*)(C + (size_t)row1 * Nbig + col) = make_float2(v10 + r1.x, v11 + r1.y);
            } else if (EPI == 3) {
                float s = (col < CH) ? QSCALE : 1.0f;
                bf16* C = (bf16*)Cout;
                *(__nv_bfloat162*)(C + (size_t)row0 * Nbig + col) = __floats2bfloat162_rn(v00 * s, v01 * s);
                *(__nv_bfloat162*)(C + (size_t)row1 * Nbig + col) = __floats2bfloat162_rn(v10 * s, v11 * s);
            } else { // EPI == 4: proj: permute rows to token order, add x, write x1
                int t0 = row2tok(row0), t1 = row2tok(row1);
                float2 r0 = *(const float2*)(res + (size_t)t0 * Nbig + col);
                float2 r1 = *(const float2*)(res + (size_t)t1 * Nbig + col);
                float* C = (float*)Cout;
                *(float2*)(C + (size_t)t0 * Nbig + col) = make_float2(v00 + r0.x, v01 + r0.y);
                *(float2*)(C + (size_t)t1 * Nbig + col) = make_float2(v10 + r1.x, v11 + r1.y);
            }
        }
    }
}

// ---------------------------------------------------------------------------
// K3: attention with mma.sync.  One CTA per window, 384 thr = 2 warps/head.
// ---------------------------------------------------------------------------
#define APB 400                       // smem tile row pitch (bytes)
#define ATTN_SMEM (3 * 64 * APB + 6 * 225 * 4 + 64 * 4)

__global__ void __launch_bounds__(384) attn_mma(const bf16* __restrict__ qkv,
                                                const float* __restrict__ bt,
                                                bf16* __restrict__ out) {
    extern __shared__ __align__(128) char sm[];
    const uint32_t sb = smem_u32(sm);
    const uint32_t sQ = sb, sK = sb + 64 * APB, sV = sb + 128 * APB;
    float* sbias = (float*)(sm + 3 * 64 * APB);
    int*   sreg  = (int*)(sm + 3 * 64 * APB + 6 * 225 * 4);

    const int tid  = threadIdx.x;
    const int win  = blockIdx.x;
    const int lane = tid & 31;
    const int wid  = tid >> 5;
    const int head = wid >> 1, half = wid & 1;
    const int g = lane >> 2, t4 = lane & 3;

    // stage q|k|v rows of this window into padded smem tiles
    const bf16* gbase = qkv + (size_t)win * NTOK * (3 * CH);
    #pragma unroll
    for (int i = 0; i < 12; i++) {
        int c = tid + i * 384;
        int r = c / 72, w2 = c % 72;
        int tile = w2 / 24, seg = w2 % 24;
        cpasync16(sb + tile * (64 * APB) + r * APB + seg * 16,
                  gbase + (size_t)r * (3 * CH) + tile * CH + seg * 8);
    }
    asm volatile("cp.async.commit_group;" ::: "memory");

    for (int i = tid; i < 6 * 225; i += 384) {
        int h = i / 225, p = i - h * 225;
        sbias[i] = bt[p * NHEAD + h];
    }
    if (tid < 64) {
        int wii = win & 255;
        int y = (wii >> 4) * 8 + (tid >> 3);
        int x = (wii & 15) * 8 + (tid & 7);
        int ry = (y < 120) ? 0 : (y < 124 ? 1 : 2);
        int rx = (x < 120) ? 0 : (x < 124 ? 1 : 2);
        sreg[tid] = ry * 3 + rx;
    }
    asm volatile("cp.async.wait_group 0;" ::: "memory");
    __syncthreads();

    const int aRow = (lane & 7) + ((lane >> 3) & 1) * 8;
    const int aCol = (lane >> 4) * 8;
    const int bRow = (lane & 7) + (lane >> 4) * 8;
    const int bCol = ((lane >> 3) & 1) * 8;

    // Q fragments (this warp's 32 rows, this head's 32 dims)
    uint32_t qf[2][2][4];
    #pragma unroll
    for (int mt = 0; mt < 2; mt++)
        #pragma unroll
        for (int ks = 0; ks < 2; ks++)
            ldm_x4(qf[mt][ks],
                   sQ + (half * 32 + mt * 16 + aRow) * APB + (head * 32 + ks * 16 + aCol) * 2);

    // scores = Q K^T
    float sc[2][8][4];
    #pragma unroll
    for (int a = 0; a < 2; a++)
        #pragma unroll
        for (int b2 = 0; b2 < 8; b2++)
            #pragma unroll
            for (int c2 = 0; c2 < 4; c2++) sc[a][b2][c2] = 0.f;

    #pragma unroll
    for (int nt = 0; nt < 4; nt++) {
        uint32_t kb[2][4];
        #pragma unroll
        for (int ks = 0; ks < 2; ks++)
            ldm_x4(kb[ks], sK + (nt * 16 + bRow) * APB + (head * 32 + ks * 16 + bCol) * 2);
        #pragma unroll
        for (int mt = 0; mt < 2; mt++)
            #pragma unroll
            for (int ks = 0; ks < 2; ks++) {
                mma16816(sc[mt][2 * nt + 0], qf[mt][ks], kb[ks] + 0);
                mma16816(sc[mt][2 * nt + 1], qf[mt][ks], kb[ks] + 2);
            }
    }

    // bias + mask + softmax (fragment-resident)
    const float* bh = sbias + head * 225;
    float inv[2][2];
    #pragma unroll
    for (int mt = 0; mt < 2; mt++) {
        #pragma unroll
        for (int s = 0; s < 2; s++) {
            int row = half * 32 + mt * 16 + g + 8 * s;
            int ty = row >> 3, tx = row & 7;
            int myreg = sreg[row];
            float mx = -1e30f;
            #pragma unroll
            for (int nt = 0; nt < 8; nt++)
                #pragma unroll
                for (int i = 0; i < 2; i++) {
                    int col = nt * 8 + t4 * 2 + i;
                    float v = sc[mt][nt][2 * s + i]
                            + bh[(ty - (col >> 3) + 7) * 15 + (tx - (col & 7) + 7)];
                    if (sreg[col] != myreg) v -= 100.f;
                    sc[mt][nt][2 * s + i] = v;
                    mx = fmaxf(mx, v);
                }
            mx = fmaxf(mx, __shfl_xor_sync(~0u, mx, 1));
            mx = fmaxf(mx, __shfl_xor_sync(~0u, mx, 2));
            float sum = 0.f;
            #pragma unroll
            for (int nt = 0; nt < 8; nt++)
                #pragma unroll
                for (int i = 0; i < 2; i++) {
                    float e = __expf(sc[mt][nt][2 * s + i] - mx);
                    sc[mt][nt][2 * s + i] = e;
                    sum += e;
                }
            sum += __shfl_xor_sync(~0u, sum, 1);
            sum += __shfl_xor_sync(~0u, sum, 2);
            inv[mt][s] = 1.0f / sum;
        }
    }

    // pack P into A fragments (normalized, bf16)
    uint32_t pf[2][4][4];
    #pragma unroll
    for (int mt = 0; mt < 2; mt++)
        #pragma unroll
        for (int kt = 0; kt < 4; kt++) {
            pf[mt][kt][0] = packbf(sc[mt][2 * kt][0] * inv[mt][0], sc[mt][2 * kt][1] * inv[mt][0]);
            pf[mt][kt][1] = packbf(sc[mt][2 * kt][2] * inv[mt][1], sc[mt][2 * kt][3] * inv[mt][1]);
            pf[mt][kt][2] = packbf(sc[mt][2 * kt + 1][0] * inv[mt][0], sc[mt][2 * kt + 1][1] * inv[mt][0]);
            pf[mt][kt][3] = packbf(sc[mt][2 * kt + 1][2] * inv[mt][1], sc[mt][2 * kt + 1][3] * inv[mt][1]);
        }

    // O = P V  (V via ldmatrix.trans)
    float o[2][4][4];
    #pragma unroll
    for (int a = 0; a < 2; a++)
        #pragma unroll
        for (int b2 = 0; b2 < 4; b2++)
            #pragma unroll
            for (int c2 = 0; c2 < 4; c2++) o[a][b2][c2] = 0.f;

    #pragma unroll
    for (int kt = 0; kt < 4; kt++)
        #pragma unroll
        for (int nv = 0; nv < 2; nv++) {
            uint32_t vb[4];
            ldm_x4t(vb, sV + (kt * 16 + (lane & 7) + ((lane >> 3) & 1) * 8) * APB
                       + (head * 32 + nv * 16 + (lane >> 4) * 8) * 2);
            #pragma unroll
            for (int mt = 0; mt < 2; mt++) {
                mma16816(o[mt][2 * nv + 0], pf[mt][kt], vb + 0);
                mma16816(o[mt][2 * nv + 1], pf[mt][kt], vb + 2);
            }
        }

    // store bf16
    bf16* ob = out + (size_t)win * NTOK * CH + head * HD;
    #pragma unroll
    for (int mt = 0; mt < 2; mt++)
        #pragma unroll
        for (int nv = 0; nv < 4; nv++) {
            int r0 = half * 32 + mt * 16 + g;
            int co = nv * 8 + t4 * 2;
            *(__nv_bfloat162*)(ob + (size_t)r0 * CH + co) =
                __floats2bfloat162_rn(o[mt][nv][0], o[mt][nv][1]);
            *(__nv_bfloat162*)(ob + (size_t)(r0 + 8) * CH + co) =
                __floats2bfloat162_rn(o[mt][nv][2], o[mt][nv][3]);
        }
}

// ---------------------------------------------------------------------------
// launch
// ---------------------------------------------------------------------------
extern "C" void kernel_launch(void* const* d_in, const int* in_sizes, int n_in,
                              void* d_out, int out_size) {
    (void)in_sizes; (void)n_in; (void)out_size;
    const float* x     = (const float*)d_in[0];
    const float* n1g   = (const float*)d_in[3];
    const float* n1b   = (const float*)d_in[4];
    const float* qkvw  = (const float*)d_in[5];
    const float* qkvb  = (const float*)d_in[6];
    const float* projw = (const float*)d_in[7];
    const float* projb = (const float*)d_in[8];
    const float* rbt   = (const float*)d_in[9];
    const float* n2g   = (const float*)d_in[10];
    const float* n2b   = (const float*)d_in[11];
    const float* fc1w  = (const float*)d_in[12];
    const float* fc1b  = (const float*)d_in[13];
    const float* fc2w  = (const float*)d_in[14];
    const float* fc2b  = (const float*)d_in[15];
    float* out = (float*)d_out;

    bf16 *xw, *qkvb2, *attnb, *ln2, *h1, *wqkv, *wproj, *wfc1, *wfc2;
    float *x1;
    cudaGetSymbolAddress((void**)&xw,    g_xw);
    cudaGetSymbolAddress((void**)&qkvb2, g_qkvb);
    cudaGetSymbolAddress((void**)&attnb, g_attn);
    cudaGetSymbolAddress((void**)&x1,    g_x1);
    cudaGetSymbolAddress((void**)&ln2,   g_ln2);
    cudaGetSymbolAddress((void**)&h1,    g_h1);
    cudaGetSymbolAddress((void**)&wqkv,  g_wqkv);
    cudaGetSymbolAddress((void**)&wproj, g_wproj);
    cudaGetSymbolAddress((void**)&wfc1,  g_wfc1);
    cudaGetSymbolAddress((void**)&wfc2,  g_wfc2);

    cudaFuncSetAttribute(attn_mma, cudaFuncAttributeMaxDynamicSharedMemorySize, ATTN_SMEM);

    wconv_kernel<<<(3 * CH * CH + 255) / 256, 256>>>(qkvw, wqkv, CH, 3 * CH);
    wconv_kernel<<<(CH * CH + 255) / 256, 256>>>(projw, wproj, CH, CH);
    wconv_kernel<<<(HID * CH + 255) / 256, 256>>>(fc1w, wfc1, CH, HID);
    wconv_kernel<<<(CH * HID + 255) / 256, 256>>>(fc2w, wfc2, HID, CH);

    // 1. LN1 + shift + partition
    ln1_kernel<<<TOT / 8, 256>>>(x, n1g, n1b, xw);

    // 2. qkv GEMM -> bf16, q pre-scaled
    hgemm<3><<<dim3((3 * CH) / 64, TOT / 128), 256>>>(xw, wqkv, qkvb, nullptr, qkvb2, CH, 3 * CH);

    // 3. attention (tensor cores)
    attn_mma<<<NWIN, 384, ATTN_SMEM>>>(qkvb2, rbt, attnb);

    // 4. proj GEMM + window-reverse + roll + residual -> x1 (token order)
    hgemm<4><<<dim3(CH / 64, TOT / 128), 256>>>(attnb, wproj, projb, x, x1, CH, CH);

    // 5. LN2
    ln2_kernel<<<TOT / 8, 256>>>(x1, n2g, n2b, ln2);

    // 6. fc1 + gelu -> bf16
    hgemm<1><<<dim3(HID / 64, TOT / 128), 256>>>(ln2, wfc1, fc1b, nullptr, h1, CH, HID);

    // 7. fc2 + residual -> out
    hgemm<2><<<dim3(CH / 64, TOT / 128), 256>>>(h1, wfc2, fc2b, x1, out, HID, CH);
}